// round 12
// baseline (speedup 1.0000x reference)
#include <cuda_runtime.h>
#include <math.h>

#define NN 100000   // nodes
#define NF 128      // in feats
#define NH 256      // hidden
#define NC 40       // classes
#define NE 800000   // edges

// ---------------- scratch (static device memory; no allocs) ----------------
// Declared as float4 to guarantee 16B alignment for vector atomics.
__device__ float  g_deg  [NN];
__device__ float  g_dinv [NN];
__device__ float4 g_aggx4[NN * NF / 4];   // 51.2 MB : (A~ x)
__device__ float4 g_h4   [NN * NH / 4];   // 102.4 MB: relu((A~x)W1 + b1)
__device__ float4 g_g4   [NN * NC / 4];   // 16 MB  : h @ W2

// 128-bit reduction-add (sm_90+), no return: avoids header-overload doubt.
__device__ __forceinline__ void red_add_f32x4(float4* p, float a, float b, float c, float d) {
    asm volatile("red.global.add.v4.f32 [%0], {%1, %2, %3, %4};"
                 :: "l"(p), "f"(a), "f"(b), "f"(c), "f"(d) : "memory");
}

// ---------------- degree / normalization ----------------
__global__ void k_deg_init() {
    int i = blockIdx.x * blockDim.x + threadIdx.x;
    if (i < NN) g_deg[i] = 1.0f;               // self-loop
}
__global__ void k_deg_count(const int* __restrict__ dst) {
    int e = blockIdx.x * blockDim.x + threadIdx.x;
    if (e < NE) atomicAdd(&g_deg[dst[e]], 1.0f);
}
__global__ void k_dinv() {
    int i = blockIdx.x * blockDim.x + threadIdx.x;
    if (i < NN) g_dinv[i] = rsqrtf(g_deg[i]);
}

// ---------------- layer-1 aggregation of x (128 feats) ----------------
// self-loop term initializes the accumulator: agg[i] = dinv[i]^2 * x[i]
__global__ void k_self_x(const float* __restrict__ x) {
    int idx = blockIdx.x * blockDim.x + threadIdx.x;   // NN * 32 float4 chunks
    if (idx >= NN * (NF / 4)) return;
    int node = idx >> 5;                               // /32
    float s = g_dinv[node]; s *= s;
    float4 v = ((const float4*)x)[idx];
    g_aggx4[idx] = make_float4(v.x * s, v.y * s, v.z * s, v.w * s);
}
// one warp per edge; lane handles one float4 of the 128-float row
__global__ void k_scatter_x(const float* __restrict__ x,
                            const int* __restrict__ src,
                            const int* __restrict__ dst) {
    int t = blockIdx.x * blockDim.x + threadIdx.x;
    int e = t >> 5, lane = t & 31;
    if (e >= NE) return;
    int s = src[e], d = dst[e];
    float nrm = g_dinv[s] * g_dinv[d];
    float4 v = ((const float4*)x)[s * (NF / 4) + lane];
    red_add_f32x4(g_aggx4 + d * (NF / 4) + lane,
                  v.x * nrm, v.y * nrm, v.z * nrm, v.w * nrm);
}

// ---------------- tiled SGEMM: C[M,N] = A[M,K] @ B[K,N] (+bias)(+relu) ------
// BM=128, BN=64, BK=8, TM=8, TN=4, 256 threads. K % 8 == 0, N % 4 == 0.
template<bool BIAS, bool RELU>
__global__ void __launch_bounds__(256)
k_sgemm(const float* __restrict__ A, const float* __restrict__ B,
        const float* __restrict__ bias, float* __restrict__ C,
        int M, int N, int K) {
    constexpr int BM = 128, BN = 64, BK = 8, TM = 8, TN = 4;
    __shared__ float As[BK][BM];
    __shared__ float Bs[BK][BN];
    const int tid = threadIdx.x;
    const int tx = tid % (BN / TN);          // 0..15 (cols)
    const int ty = tid / (BN / TN);          // 0..15 (rows)
    const int rowBase = blockIdx.y * BM;
    const int colBase = blockIdx.x * BN;

    const int aRow = tid / (BK / 4);         // 0..127
    const int aCol = (tid % (BK / 4)) * 4;   // 0 or 4
    const int bRow = tid / (BN / 4);         // 0..7 (tid<128)
    const int bCol = (tid % (BN / 4)) * 4;   // 0..60

    float acc[TM][TN];
#pragma unroll
    for (int i = 0; i < TM; i++)
#pragma unroll
        for (int j = 0; j < TN; j++) acc[i][j] = 0.f;

    for (int kk = 0; kk < K; kk += BK) {
        float4 av = make_float4(0.f, 0.f, 0.f, 0.f);
        int gr = rowBase + aRow;
        if (gr < M) av = *(const float4*)&A[(size_t)gr * K + kk + aCol];
        As[aCol + 0][aRow] = av.x;
        As[aCol + 1][aRow] = av.y;
        As[aCol + 2][aRow] = av.z;
        As[aCol + 3][aRow] = av.w;
        if (tid < BK * BN / 4) {
            int gc = colBase + bCol;
            float4 bv = make_float4(0.f, 0.f, 0.f, 0.f);
            if (gc < N) bv = *(const float4*)&B[(size_t)(kk + bRow) * N + gc];
            *(float4*)&Bs[bRow][bCol] = bv;
        }
        __syncthreads();
#pragma unroll
        for (int k = 0; k < BK; k++) {
            float ra[TM], rb[TN];
#pragma unroll
            for (int i = 0; i < TM; i += 4)
                *(float4*)&ra[i] = *(const float4*)&As[k][ty * TM + i];
            *(float4*)&rb[0] = *(const float4*)&Bs[k][tx * TN];
#pragma unroll
            for (int i = 0; i < TM; i++)
#pragma unroll
                for (int j = 0; j < TN; j++)
                    acc[i][j] = fmaf(ra[i], rb[j], acc[i][j]);
        }
        __syncthreads();
    }
#pragma unroll
    for (int i = 0; i < TM; i++) {
        int r = rowBase + ty * TM + i;
        if (r >= M) continue;
#pragma unroll
        for (int j = 0; j < TN; j++) {
            int c = colBase + tx * TN + j;
            if (c >= N) continue;
            float v = acc[i][j];
            if (BIAS) v += bias[c];
            if (RELU) v = fmaxf(v, 0.f);
            C[(size_t)r * N + c] = v;
        }
    }
}

// ---------------- layer-2 aggregation of g (40 feats) -> out ----------------
__global__ void k_self_g(float* __restrict__ out) {
    int idx = blockIdx.x * blockDim.x + threadIdx.x;   // NN * 10 chunks
    if (idx >= NN * (NC / 4)) return;
    int node = idx / (NC / 4);
    float s = g_dinv[node]; s *= s;
    float4 v = g_g4[idx];
    ((float4*)out)[idx] = make_float4(v.x * s, v.y * s, v.z * s, v.w * s);
}
__global__ void k_scatter_g(const int* __restrict__ src,
                            const int* __restrict__ dst,
                            float* __restrict__ out) {
    int idx = blockIdx.x * blockDim.x + threadIdx.x;   // NE * 10 chunks
    if (idx >= NE * (NC / 4)) return;
    int e = idx / (NC / 4);
    int c = idx - e * (NC / 4);
    int s = src[e], d = dst[e];
    float nrm = g_dinv[s] * g_dinv[d];
    float4 v = g_g4[s * (NC / 4) + c];
    red_add_f32x4(((float4*)out) + d * (NC / 4) + c,
                  v.x * nrm, v.y * nrm, v.z * nrm, v.w * nrm);
}

// ---------------- +b2 and log_softmax, in place, warp per row --------------
__global__ void k_logsoftmax(float* __restrict__ out, const float* __restrict__ b2) {
    int t = blockIdx.x * blockDim.x + threadIdx.x;
    int r = t >> 5, lane = t & 31;
    if (r >= NN) return;
    float* row = out + (size_t)r * NC;
    float v0 = row[lane] + b2[lane];                          // cols 0..31
    float v1 = (lane < NC - 32) ? row[32 + lane] + b2[32 + lane] : -INFINITY;
    float m = fmaxf(v0, v1);
#pragma unroll
    for (int o = 16; o; o >>= 1) m = fmaxf(m, __shfl_xor_sync(0xffffffffu, m, o));
    float s = expf(v0 - m) + ((lane < NC - 32) ? expf(v1 - m) : 0.f);
#pragma unroll
    for (int o = 16; o; o >>= 1) s += __shfl_xor_sync(0xffffffffu, s, o);
    float lse = m + logf(s);
    row[lane] = v0 - lse;
    if (lane < NC - 32) row[32 + lane] = v1 - lse;
}

// ---------------- launch ----------------
extern "C" void kernel_launch(void* const* d_in, const int* in_sizes, int n_in,
                              void* d_out, int out_size) {
    const float* x  = (const float*)d_in[0];
    const int*   ei = (const int*)  d_in[1];
    const int*   src = ei;
    const int*   dst = ei + NE;
    const float* W1 = (const float*)d_in[2];
    const float* b1 = (const float*)d_in[3];
    const float* W2 = (const float*)d_in[4];
    const float* b2 = (const float*)d_in[5];
    float* out = (float*)d_out;

    // Resolve REAL device addresses of the scratch symbols. Passing the
    // __device__ symbol name from host code passes the host shadow address
    // (which GB300's ATS happily dereferences as zeros — the round-11 bug).
    // cudaGetSymbolAddress is not a stream op: graph-capture-safe, and the
    // resolved addresses are baked into the captured kernel nodes.
    void *p_aggx = nullptr, *p_h = nullptr, *p_g = nullptr;
    cudaGetSymbolAddress(&p_aggx, g_aggx4);
    cudaGetSymbolAddress(&p_h,    g_h4);
    cudaGetSymbolAddress(&p_g,    g_g4);
    float* aggx = (float*)p_aggx;
    float* h    = (float*)p_h;
    float* g    = (float*)p_g;

    // degrees / dinv
    k_deg_init<<<(NN + 255) / 256, 256>>>();
    k_deg_count<<<(NE + 255) / 256, 256>>>(dst);
    k_dinv<<<(NN + 255) / 256, 256>>>();

    // layer 1: agg_x = A~ x   (aggregate BEFORE the GEMM: 128-wide)
    k_self_x<<<(NN * (NF / 4) + 255) / 256, 256>>>(x);
    k_scatter_x<<<(NE * 32 + 255) / 256, 256>>>(x, src, dst);

    // h = relu(agg_x @ W1 + b1)   [100000x128 @ 128x256]
    {
        dim3 grid(NH / 64, (NN + 127) / 128);
        k_sgemm<true, true><<<grid, 256>>>(aggx, W1, b1, h, NN, NH, NF);
    }

    // layer 2: g = h @ W2   [100000x256 @ 256x40]  (GEMM BEFORE aggregation)
    {
        dim3 grid(1, (NN + 127) / 128);
        k_sgemm<false, false><<<grid, 256>>>(h, W2, nullptr, g, NN, NC, NH);
    }

    // out = A~ g  (40-wide aggregation directly into d_out)
    k_self_g<<<(NN * (NC / 4) + 255) / 256, 256>>>(out);
    k_scatter_g<<<(NE * (NC / 4) + 255) / 256, 256>>>(src, dst, out);

    // out = log_softmax(out + b2)
    k_logsoftmax<<<(NN * 32 + 255) / 256, 256>>>(out, b2);
}

// round 14
// speedup vs baseline: 1.1221x; 1.1221x over previous
#include <cuda_runtime.h>
#include <math.h>
#include <stdint.h>

#define NN 100000   // nodes
#define NF 128      // in feats
#define NH 256      // hidden
#define NC 40       // classes
#define NE 800000   // edges

// ---------------- scratch (static device memory; no allocs) ----------------
__device__ float  g_deg  [NN];
__device__ float  g_dinv [NN];
__device__ float4 g_aggx4[NN * NF / 4];   // 51.2 MB : (A~ x)
__device__ float4 g_h4   [NN * NH / 4];   // 102.4 MB: relu((A~x)W1 + b1)
__device__ float4 g_g4   [NN * NC / 4];   // 16 MB  : h @ W2

// ---------------- base-target PTX helpers (no sm_103a-only features) -------
__device__ __forceinline__ void red_add_f32x4(float4* p, float a, float b, float c, float d) {
    asm volatile("red.global.add.v4.f32 [%0], {%1, %2, %3, %4};"
                 :: "l"(p), "f"(a), "f"(b), "f"(c), "f"(d) : "memory");
}
// 3xTF32 split: hi = rna_tf32(a), lo = rna_tf32(a - hi)
__device__ __forceinline__ void split_tf32(float a, uint32_t& hi, uint32_t& lo) {
    asm("cvt.rna.tf32.f32 %0, %1;" : "=r"(hi) : "f"(a));
    float r = a - __uint_as_float(hi);
    asm("cvt.rna.tf32.f32 %0, %1;" : "=r"(lo) : "f"(r));
}
// D(16x8,f32) += A(16x8,tf32 row) * B(8x8,tf32 col)
__device__ __forceinline__ void mma16n8k8(float* d, const uint32_t* a, const uint32_t* b) {
    asm volatile(
        "mma.sync.aligned.m16n8k8.row.col.f32.tf32.tf32.f32 "
        "{%0,%1,%2,%3}, {%4,%5,%6,%7}, {%8,%9}, {%0,%1,%2,%3};"
        : "+f"(d[0]), "+f"(d[1]), "+f"(d[2]), "+f"(d[3])
        : "r"(a[0]), "r"(a[1]), "r"(a[2]), "r"(a[3]), "r"(b[0]), "r"(b[1]));
}

// ---------------- degree / normalization ----------------
__global__ void k_deg_init() {
    int i = blockIdx.x * blockDim.x + threadIdx.x;
    if (i < NN) g_deg[i] = 1.0f;               // self-loop
}
__global__ void k_deg_count(const int* __restrict__ dst) {
    int e = blockIdx.x * blockDim.x + threadIdx.x;
    if (e < NE) atomicAdd(&g_deg[dst[e]], 1.0f);
}
__global__ void k_dinv() {
    int i = blockIdx.x * blockDim.x + threadIdx.x;
    if (i < NN) g_dinv[i] = rsqrtf(g_deg[i]);
}

// ---------------- layer-1 aggregation of x (128 feats) ----------------
__global__ void k_self_x(const float* __restrict__ x) {
    int idx = blockIdx.x * blockDim.x + threadIdx.x;
    if (idx >= NN * (NF / 4)) return;
    int node = idx >> 5;
    float s = g_dinv[node]; s *= s;
    float4 v = ((const float4*)x)[idx];
    g_aggx4[idx] = make_float4(v.x * s, v.y * s, v.z * s, v.w * s);
}
__global__ void k_scatter_x(const float* __restrict__ x,
                            const int* __restrict__ src,
                            const int* __restrict__ dst) {
    int t = blockIdx.x * blockDim.x + threadIdx.x;
    int e = t >> 5, lane = t & 31;
    if (e >= NE) return;
    int s = src[e], d = dst[e];
    float nrm = g_dinv[s] * g_dinv[d];
    float4 v = ((const float4*)x)[s * (NF / 4) + lane];
    red_add_f32x4(g_aggx4 + d * (NF / 4) + lane,
                  v.x * nrm, v.y * nrm, v.z * nrm, v.w * nrm);
}

// ---------------- warp-MMA tf32 GEMM (3xTF32 split) ----------------
// C[M,N] = A[M,K] @ Bw[K,N] (+bias)(+relu). CTA tile 128x64, 8 warps (4x2),
// warp tile 32x32, K staged in 32-wide chunks (hi/lo planes in SMEM).
// SMEM row stride 36 words => conflict-free fragment loads.
#define STR 36
template<bool BIAS, bool RELU>
__global__ void __launch_bounds__(256)
k_mma_gemm(const float* __restrict__ A, const float* __restrict__ Bw,
           const float* __restrict__ bias, float* __restrict__ C,
           int M, int N, int K) {
    extern __shared__ float sm[];
    float* As_hi = sm;                    // [128][STR]
    float* As_lo = As_hi + 128 * STR;
    float* Bs_hi = As_lo + 128 * STR;     // [64][STR]
    float* Bs_lo = Bs_hi + 64 * STR;

    const int tid = threadIdx.x;
    const int wid = tid >> 5, lid = tid & 31;
    const int wm = wid & 3, wn = wid >> 2;          // warp grid 4(m) x 2(n)
    const int g = lid >> 2, tig = lid & 3;
    const int mBase = blockIdx.y * 128;
    const int colBase = blockIdx.x * 64;

    float d[2][4][4];
#pragma unroll
    for (int a = 0; a < 2; a++)
#pragma unroll
        for (int b = 0; b < 4; b++)
#pragma unroll
            for (int c = 0; c < 4; c++) d[a][b][c] = 0.f;

    const int KB = K >> 5;
    for (int kb = 0; kb < KB; kb++) {
        // stage A chunk: 128 rows x 32 cols (float4 gmem, hi/lo split)
        for (int i = tid; i < 1024; i += 256) {
            int m = i >> 3, q = (i & 7) << 2;
            int gm = mBase + m;
            float4 v = make_float4(0.f, 0.f, 0.f, 0.f);
            if (gm < M) v = *(const float4*)&A[(size_t)gm * K + (kb << 5) + q];
            uint32_t h0, l0, h1, l1, h2, l2, h3, l3;
            split_tf32(v.x, h0, l0); split_tf32(v.y, h1, l1);
            split_tf32(v.z, h2, l2); split_tf32(v.w, h3, l3);
            float* ph = As_hi + m * STR + q;
            float* pl = As_lo + m * STR + q;
            ph[0] = __uint_as_float(h0); ph[1] = __uint_as_float(h1);
            ph[2] = __uint_as_float(h2); ph[3] = __uint_as_float(h3);
            pl[0] = __uint_as_float(l0); pl[1] = __uint_as_float(l1);
            pl[2] = __uint_as_float(l2); pl[3] = __uint_as_float(l3);
        }
        // stage B chunk transposed: Bs[n][k] = Bw[k][colBase+n]
        for (int i = tid; i < 2048; i += 256) {
            int kc = i >> 6, n = i & 63;
            int gn = colBase + n;
            float v = (gn < N) ? Bw[(size_t)((kb << 5) + kc) * N + gn] : 0.f;
            uint32_t hi, lo; split_tf32(v, hi, lo);
            Bs_hi[n * STR + kc] = __uint_as_float(hi);
            Bs_lo[n * STR + kc] = __uint_as_float(lo);
        }
        __syncthreads();

#pragma unroll
        for (int ks = 0; ks < 4; ks++) {
            const int k0 = (ks << 3) + tig;
            uint32_t ah[2][4], al[2][4], bh[4][2], bl[4][2];
#pragma unroll
            for (int im = 0; im < 2; im++) {
                int r0 = (wm * 32 + im * 16 + g) * STR;
                ah[im][0] = __float_as_uint(As_hi[r0 + k0]);
                ah[im][1] = __float_as_uint(As_hi[r0 + 8 * STR + k0]);
                ah[im][2] = __float_as_uint(As_hi[r0 + k0 + 4]);
                ah[im][3] = __float_as_uint(As_hi[r0 + 8 * STR + k0 + 4]);
                al[im][0] = __float_as_uint(As_lo[r0 + k0]);
                al[im][1] = __float_as_uint(As_lo[r0 + 8 * STR + k0]);
                al[im][2] = __float_as_uint(As_lo[r0 + k0 + 4]);
                al[im][3] = __float_as_uint(As_lo[r0 + 8 * STR + k0 + 4]);
            }
#pragma unroll
            for (int in_ = 0; in_ < 4; in_++) {
                int n0 = (wn * 32 + in_ * 8 + g) * STR;
                bh[in_][0] = __float_as_uint(Bs_hi[n0 + k0]);
                bh[in_][1] = __float_as_uint(Bs_hi[n0 + k0 + 4]);
                bl[in_][0] = __float_as_uint(Bs_lo[n0 + k0]);
                bl[in_][1] = __float_as_uint(Bs_lo[n0 + k0 + 4]);
            }
#pragma unroll
            for (int im = 0; im < 2; im++)
#pragma unroll
                for (int in_ = 0; in_ < 4; in_++)
                    mma16n8k8(d[im][in_], ah[im], bh[in_]);
#pragma unroll
            for (int im = 0; im < 2; im++)
#pragma unroll
                for (int in_ = 0; in_ < 4; in_++)
                    mma16n8k8(d[im][in_], ah[im], bl[in_]);
#pragma unroll
            for (int im = 0; im < 2; im++)
#pragma unroll
                for (int in_ = 0; in_ < 4; in_++)
                    mma16n8k8(d[im][in_], al[im], bh[in_]);
        }
        __syncthreads();
    }

    // epilogue
#pragma unroll
    for (int im = 0; im < 2; im++) {
        int r0 = mBase + wm * 32 + im * 16 + g;
        int r1 = r0 + 8;
#pragma unroll
        for (int in_ = 0; in_ < 4; in_++) {
            int c = colBase + wn * 32 + in_ * 8 + 2 * tig;
            if (c >= N) continue;
            float bx = 0.f, by = 0.f;
            if (BIAS) { bx = bias[c]; by = bias[c + 1]; }
            float v0 = d[im][in_][0] + bx, v1 = d[im][in_][1] + by;
            float v2 = d[im][in_][2] + bx, v3 = d[im][in_][3] + by;
            if (RELU) {
                v0 = fmaxf(v0, 0.f); v1 = fmaxf(v1, 0.f);
                v2 = fmaxf(v2, 0.f); v3 = fmaxf(v3, 0.f);
            }
            if (r0 < M) *(float2*)&C[(size_t)r0 * N + c] = make_float2(v0, v1);
            if (r1 < M) *(float2*)&C[(size_t)r1 * N + c] = make_float2(v2, v3);
        }
    }
}

// ---------------- layer-2 aggregation of g (40 feats) -> out ----------------
__global__ void k_self_g(float* __restrict__ out) {
    int idx = blockIdx.x * blockDim.x + threadIdx.x;
    if (idx >= NN * (NC / 4)) return;
    int node = idx / (NC / 4);
    float s = g_dinv[node]; s *= s;
    float4 v = g_g4[idx];
    ((float4*)out)[idx] = make_float4(v.x * s, v.y * s, v.z * s, v.w * s);
}
__global__ void k_scatter_g(const int* __restrict__ src,
                            const int* __restrict__ dst,
                            float* __restrict__ out) {
    int idx = blockIdx.x * blockDim.x + threadIdx.x;
    if (idx >= NE * (NC / 4)) return;
    int e = idx / (NC / 4);
    int c = idx - e * (NC / 4);
    int s = src[e], d = dst[e];
    float nrm = g_dinv[s] * g_dinv[d];
    float4 v = g_g4[s * (NC / 4) + c];
    red_add_f32x4(((float4*)out) + d * (NC / 4) + c,
                  v.x * nrm, v.y * nrm, v.z * nrm, v.w * nrm);
}

// ---------------- +b2 and log_softmax, in place, warp per row --------------
__global__ void k_logsoftmax(float* __restrict__ out, const float* __restrict__ b2) {
    int t = blockIdx.x * blockDim.x + threadIdx.x;
    int r = t >> 5, lane = t & 31;
    if (r >= NN) return;
    float* row = out + (size_t)r * NC;
    float v0 = row[lane] + b2[lane];
    float v1 = (lane < NC - 32) ? row[32 + lane] + b2[32 + lane] : -INFINITY;
    float m = fmaxf(v0, v1);
#pragma unroll
    for (int o = 16; o; o >>= 1) m = fmaxf(m, __shfl_xor_sync(0xffffffffu, m, o));
    float s = expf(v0 - m) + ((lane < NC - 32) ? expf(v1 - m) : 0.f);
#pragma unroll
    for (int o = 16; o; o >>= 1) s += __shfl_xor_sync(0xffffffffu, s, o);
    float lse = m + logf(s);
    row[lane] = v0 - lse;
    if (lane < NC - 32) row[32 + lane] = v1 - lse;
}

// ---------------- launch ----------------
extern "C" void kernel_launch(void* const* d_in, const int* in_sizes, int n_in,
                              void* d_out, int out_size) {
    const float* x  = (const float*)d_in[0];
    const int*   ei = (const int*)  d_in[1];
    const int*   src = ei;
    const int*   dst = ei + NE;
    const float* W1 = (const float*)d_in[2];
    const float* b1 = (const float*)d_in[3];
    const float* W2 = (const float*)d_in[4];
    const float* b2 = (const float*)d_in[5];
    float* out = (float*)d_out;

    // Resolve REAL device addresses of scratch (host shadow trap — round 11).
    void *p_aggx = nullptr, *p_h = nullptr, *p_g = nullptr;
    cudaGetSymbolAddress(&p_aggx, g_aggx4);
    cudaGetSymbolAddress(&p_h,    g_h4);
    cudaGetSymbolAddress(&p_g,    g_g4);
    float* aggx = (float*)p_aggx;
    float* h    = (float*)p_h;
    float* g    = (float*)p_g;

    // dynamic smem: (128 + 128 + 64 + 64) * 36 floats = 55296 B
    const int SMEM = (128 * STR * 2 + 64 * STR * 2) * sizeof(float);
    cudaFuncSetAttribute(k_mma_gemm<true,  true >,
                         cudaFuncAttributeMaxDynamicSharedMemorySize, SMEM);
    cudaFuncSetAttribute(k_mma_gemm<false, false>,
                         cudaFuncAttributeMaxDynamicSharedMemorySize, SMEM);

    // degrees / dinv
    k_deg_init<<<(NN + 255) / 256, 256>>>();
    k_deg_count<<<(NE + 255) / 256, 256>>>(dst);
    k_dinv<<<(NN + 255) / 256, 256>>>();

    // layer 1: agg_x = A~ x   (aggregate BEFORE the GEMM: 128-wide)
    k_self_x<<<(NN * (NF / 4) + 255) / 256, 256>>>(x);
    k_scatter_x<<<(NE * 32 + 255) / 256, 256>>>(x, src, dst);

    const int gridM = (NN + 127) / 128;  // 782

    // h = relu(agg_x @ W1 + b1)   [100000x128 @ 128x256]  — tf32 MMA
    {
        dim3 grid(NH / 64, gridM);
        k_mma_gemm<true, true><<<grid, 256, SMEM>>>(aggx, W1, b1, h, NN, NH, NF);
    }
    // g = h @ W2   [100000x256 @ 256x40]  — tf32 MMA (N padded to 64 tile)
    {
        dim3 grid(1, gridM);
        k_mma_gemm<false, false><<<grid, 256, SMEM>>>(h, W2, nullptr, g, NN, NC, NH);
    }

    // out = A~ g  (40-wide aggregation directly into d_out)
    k_self_g<<<(NN * (NC / 4) + 255) / 256, 256>>>(out);
    k_scatter_g<<<(NE * (NC / 4) + 255) / 256, 256>>>(src, dst, out);

    // out = log_softmax(out + b2)
    k_logsoftmax<<<(NN * 32 + 255) / 256, 256>>>(out, b2);
}

// round 15
// speedup vs baseline: 1.2745x; 1.1359x over previous
#include <cuda_runtime.h>
#include <math.h>
#include <stdint.h>

#define NN 100000   // nodes
#define NF 128      // in feats
#define NH 256      // hidden
#define NC 40       // classes
#define NE 800000   // edges
#define NB ((NN + 255) / 256)   // 391 scan blocks

// ---------------- scratch (static device memory; no allocs) ----------------
__device__ float  g_dinv [NN];
__device__ int    g_cnt  [NN];        // in-degree histogram (no self loop)
__device__ int    g_off  [NN];        // CSR row starts
__device__ int    g_cur  [NN];        // fill cursors
__device__ int    g_adj  [NE];        // CSR column (src) indices
__device__ int    g_bsum [NB + 1];
__device__ int    g_boff [NB + 1];
__device__ float4 g_aggx4[NN * NF / 4];   // 51.2 MB : (A~ x)
__device__ float4 g_h4   [NN * NH / 4];   // 102.4 MB: relu((A~x)W1 + b1)
__device__ float4 g_g4   [NN * NC / 4];   // 16 MB  : h @ W2

// ---------------- base-target PTX helpers ----------------
// 3xTF32 split: hi = rna_tf32(a), lo = rna_tf32(a - hi)
__device__ __forceinline__ void split_tf32(float a, uint32_t& hi, uint32_t& lo) {
    asm("cvt.rna.tf32.f32 %0, %1;" : "=r"(hi) : "f"(a));
    float r = a - __uint_as_float(hi);
    asm("cvt.rna.tf32.f32 %0, %1;" : "=r"(lo) : "f"(r));
}
// D(16x8,f32) += A(16x8,tf32 row) * B(8x8,tf32 col)
__device__ __forceinline__ void mma16n8k8(float* d, const uint32_t* a, const uint32_t* b) {
    asm volatile(
        "mma.sync.aligned.m16n8k8.row.col.f32.tf32.tf32.f32 "
        "{%0,%1,%2,%3}, {%4,%5,%6,%7}, {%8,%9}, {%0,%1,%2,%3};"
        : "+f"(d[0]), "+f"(d[1]), "+f"(d[2]), "+f"(d[3])
        : "r"(a[0]), "r"(a[1]), "r"(a[2]), "r"(a[3]), "r"(b[0]), "r"(b[1]));
}

// ---------------- CSR build ----------------
__global__ void k_zero() {
    int i = blockIdx.x * blockDim.x + threadIdx.x;
    if (i < NN) g_cnt[i] = 0;
}
__global__ void k_hist(const int* __restrict__ dst) {
    int e = blockIdx.x * blockDim.x + threadIdx.x;
    if (e < NE) atomicAdd(&g_cnt[dst[e]], 1);
}
__global__ void k_dinv() {
    int i = blockIdx.x * blockDim.x + threadIdx.x;
    if (i < NN) g_dinv[i] = rsqrtf((float)(g_cnt[i] + 1));   // +1 self-loop
}
// block sums of cnt (256 per block)
__global__ void k_bsum() {
    __shared__ int sh[256];
    int t = threadIdx.x, i = blockIdx.x * 256 + t;
    int v = (i < NN) ? g_cnt[i] : 0;
    sh[t] = v; __syncthreads();
    for (int off = 128; off; off >>= 1) {
        if (t < off) sh[t] += sh[t + off];
        __syncthreads();
    }
    if (t == 0) g_bsum[blockIdx.x] = sh[0];
}
// exclusive scan of block sums (single block, 512 threads covers NB=391)
__global__ void k_bscan() {
    __shared__ int sh[512];
    int t = threadIdx.x;
    int v = (t < NB) ? g_bsum[t] : 0;
    sh[t] = v; __syncthreads();
    for (int off = 1; off < 512; off <<= 1) {
        int tv = (t >= off) ? sh[t - off] : 0;
        __syncthreads();
        sh[t] += tv;
        __syncthreads();
    }
    if (t < NB) g_boff[t] = sh[t] - v;   // exclusive
}
// per-block exclusive scan + base => row offsets; also init cursors
__global__ void k_offsets() {
    __shared__ int sh[256];
    int t = threadIdx.x, i = blockIdx.x * 256 + t;
    int v = (i < NN) ? g_cnt[i] : 0;
    sh[t] = v; __syncthreads();
    for (int off = 1; off < 256; off <<= 1) {
        int tv = (t >= off) ? sh[t - off] : 0;
        __syncthreads();
        sh[t] += tv;
        __syncthreads();
    }
    if (i < NN) {
        int o = g_boff[blockIdx.x] + sh[t] - v;
        g_off[i] = o;
        g_cur[i] = o;
    }
}
__global__ void k_fill(const int* __restrict__ src, const int* __restrict__ dst) {
    int e = blockIdx.x * blockDim.x + threadIdx.x;
    if (e >= NE) return;
    int d = dst[e];
    int p = atomicAdd(&g_cur[d], 1);
    g_adj[p] = src[e];
}

// ---------------- layer-1 gather: aggx = A~ x (warp per node) --------------
__global__ void k_gather_x(const float* __restrict__ x) {
    int t = blockIdx.x * blockDim.x + threadIdx.x;
    int w = t >> 5, lane = t & 31;
    if (w >= NN) return;
    const float4* x4 = (const float4*)x;
    float di = g_dinv[w];
    float4 a = x4[(size_t)w * 32 + lane];
    float s2 = di * di;
    float ax = a.x * s2, ay = a.y * s2, az = a.z * s2, aw = a.w * s2;
    int beg = g_off[w], n = g_cnt[w];
    int j = 0;
    for (; j + 4 <= n; j += 4) {
        int s0 = g_adj[beg + j], s1 = g_adj[beg + j + 1];
        int s2i = g_adj[beg + j + 2], s3 = g_adj[beg + j + 3];
        float n0 = di * g_dinv[s0], n1 = di * g_dinv[s1];
        float n2 = di * g_dinv[s2i], n3 = di * g_dinv[s3];
        float4 v0 = x4[(size_t)s0 * 32 + lane];
        float4 v1 = x4[(size_t)s1 * 32 + lane];
        float4 v2 = x4[(size_t)s2i * 32 + lane];
        float4 v3 = x4[(size_t)s3 * 32 + lane];
        ax += v0.x * n0 + v1.x * n1 + v2.x * n2 + v3.x * n3;
        ay += v0.y * n0 + v1.y * n1 + v2.y * n2 + v3.y * n3;
        az += v0.z * n0 + v1.z * n1 + v2.z * n2 + v3.z * n3;
        aw += v0.w * n0 + v1.w * n1 + v2.w * n2 + v3.w * n3;
    }
    for (; j < n; j++) {
        int s = g_adj[beg + j];
        float nr = di * g_dinv[s];
        float4 v = x4[(size_t)s * 32 + lane];
        ax += v.x * nr; ay += v.y * nr; az += v.z * nr; aw += v.w * nr;
    }
    g_aggx4[(size_t)w * 32 + lane] = make_float4(ax, ay, az, aw);
}

// ---------------- warp-MMA tf32 GEMM (3xTF32 split) — proven round-14 ------
#define STR 36
template<bool BIAS, bool RELU>
__global__ void __launch_bounds__(256)
k_mma_gemm(const float* __restrict__ A, const float* __restrict__ Bw,
           const float* __restrict__ bias, float* __restrict__ C,
           int M, int N, int K) {
    extern __shared__ float sm[];
    float* As_hi = sm;                    // [128][STR]
    float* As_lo = As_hi + 128 * STR;
    float* Bs_hi = As_lo + 128 * STR;     // [64][STR]
    float* Bs_lo = Bs_hi + 64 * STR;

    const int tid = threadIdx.x;
    const int wid = tid >> 5, lid = tid & 31;
    const int wm = wid & 3, wn = wid >> 2;          // warp grid 4(m) x 2(n)
    const int g = lid >> 2, tig = lid & 3;
    const int mBase = blockIdx.y * 128;
    const int colBase = blockIdx.x * 64;

    float d[2][4][4];
#pragma unroll
    for (int a = 0; a < 2; a++)
#pragma unroll
        for (int b = 0; b < 4; b++)
#pragma unroll
            for (int c = 0; c < 4; c++) d[a][b][c] = 0.f;

    const int KB = K >> 5;
    for (int kb = 0; kb < KB; kb++) {
        for (int i = tid; i < 1024; i += 256) {
            int m = i >> 3, q = (i & 7) << 2;
            int gm = mBase + m;
            float4 v = make_float4(0.f, 0.f, 0.f, 0.f);
            if (gm < M) v = *(const float4*)&A[(size_t)gm * K + (kb << 5) + q];
            uint32_t h0, l0, h1, l1, h2, l2, h3, l3;
            split_tf32(v.x, h0, l0); split_tf32(v.y, h1, l1);
            split_tf32(v.z, h2, l2); split_tf32(v.w, h3, l3);
            float* ph = As_hi + m * STR + q;
            float* pl = As_lo + m * STR + q;
            ph[0] = __uint_as_float(h0); ph[1] = __uint_as_float(h1);
            ph[2] = __uint_as_float(h2); ph[3] = __uint_as_float(h3);
            pl[0] = __uint_as_float(l0); pl[1] = __uint_as_float(l1);
            pl[2] = __uint_as_float(l2); pl[3] = __uint_as_float(l3);
        }
        for (int i = tid; i < 2048; i += 256) {
            int kc = i >> 6, n = i & 63;
            int gn = colBase + n;
            float v = (gn < N) ? Bw[(size_t)((kb << 5) + kc) * N + gn] : 0.f;
            uint32_t hi, lo; split_tf32(v, hi, lo);
            Bs_hi[n * STR + kc] = __uint_as_float(hi);
            Bs_lo[n * STR + kc] = __uint_as_float(lo);
        }
        __syncthreads();

#pragma unroll
        for (int ks = 0; ks < 4; ks++) {
            const int k0 = (ks << 3) + tig;
            uint32_t ah[2][4], al[2][4], bh[4][2], bl[4][2];
#pragma unroll
            for (int im = 0; im < 2; im++) {
                int r0 = (wm * 32 + im * 16 + g) * STR;
                ah[im][0] = __float_as_uint(As_hi[r0 + k0]);
                ah[im][1] = __float_as_uint(As_hi[r0 + 8 * STR + k0]);
                ah[im][2] = __float_as_uint(As_hi[r0 + k0 + 4]);
                ah[im][3] = __float_as_uint(As_hi[r0 + 8 * STR + k0 + 4]);
                al[im][0] = __float_as_uint(As_lo[r0 + k0]);
                al[im][1] = __float_as_uint(As_lo[r0 + 8 * STR + k0]);
                al[im][2] = __float_as_uint(As_lo[r0 + k0 + 4]);
                al[im][3] = __float_as_uint(As_lo[r0 + 8 * STR + k0 + 4]);
            }
#pragma unroll
            for (int in_ = 0; in_ < 4; in_++) {
                int n0 = (wn * 32 + in_ * 8 + g) * STR;
                bh[in_][0] = __float_as_uint(Bs_hi[n0 + k0]);
                bh[in_][1] = __float_as_uint(Bs_hi[n0 + k0 + 4]);
                bl[in_][0] = __float_as_uint(Bs_lo[n0 + k0]);
                bl[in_][1] = __float_as_uint(Bs_lo[n0 + k0 + 4]);
            }
#pragma unroll
            for (int im = 0; im < 2; im++)
#pragma unroll
                for (int in_ = 0; in_ < 4; in_++)
                    mma16n8k8(d[im][in_], ah[im], bh[in_]);
#pragma unroll
            for (int im = 0; im < 2; im++)
#pragma unroll
                for (int in_ = 0; in_ < 4; in_++)
                    mma16n8k8(d[im][in_], ah[im], bl[in_]);
#pragma unroll
            for (int im = 0; im < 2; im++)
#pragma unroll
                for (int in_ = 0; in_ < 4; in_++)
                    mma16n8k8(d[im][in_], al[im], bh[in_]);
        }
        __syncthreads();
    }

#pragma unroll
    for (int im = 0; im < 2; im++) {
        int r0 = mBase + wm * 32 + im * 16 + g;
        int r1 = r0 + 8;
#pragma unroll
        for (int in_ = 0; in_ < 4; in_++) {
            int c = colBase + wn * 32 + in_ * 8 + 2 * tig;
            if (c >= N) continue;
            float bx = 0.f, by = 0.f;
            if (BIAS) { bx = bias[c]; by = bias[c + 1]; }
            float v0 = d[im][in_][0] + bx, v1 = d[im][in_][1] + by;
            float v2 = d[im][in_][2] + bx, v3 = d[im][in_][3] + by;
            if (RELU) {
                v0 = fmaxf(v0, 0.f); v1 = fmaxf(v1, 0.f);
                v2 = fmaxf(v2, 0.f); v3 = fmaxf(v3, 0.f);
            }
            if (r0 < M) *(float2*)&C[(size_t)r0 * N + c] = make_float2(v0, v1);
            if (r1 < M) *(float2*)&C[(size_t)r1 * N + c] = make_float2(v2, v3);
        }
    }
}

// ---------------- layer-2 gather: out = A~ g (2 nodes per warp) ------------
__global__ void k_gather_g(float* __restrict__ out) {
    int t = blockIdx.x * blockDim.x + threadIdx.x;
    int w = t >> 5, lane = t & 31;
    int node = w * 2 + (lane >> 4);
    int c = lane & 15;                       // float4 chunk 0..9 active
    if (node >= NN || c >= NC / 4) return;
    float di = g_dinv[node];
    float s2 = di * di;
    float4 a = g_g4[(size_t)node * (NC / 4) + c];
    float ax = a.x * s2, ay = a.y * s2, az = a.z * s2, aw = a.w * s2;
    int beg = g_off[node], n = g_cnt[node];
    int j = 0;
    for (; j + 2 <= n; j += 2) {
        int s0 = g_adj[beg + j], s1 = g_adj[beg + j + 1];
        float n0 = di * g_dinv[s0], n1 = di * g_dinv[s1];
        float4 v0 = g_g4[(size_t)s0 * (NC / 4) + c];
        float4 v1 = g_g4[(size_t)s1 * (NC / 4) + c];
        ax += v0.x * n0 + v1.x * n1; ay += v0.y * n0 + v1.y * n1;
        az += v0.z * n0 + v1.z * n1; aw += v0.w * n0 + v1.w * n1;
    }
    for (; j < n; j++) {
        int s = g_adj[beg + j];
        float nr = di * g_dinv[s];
        float4 v = g_g4[(size_t)s * (NC / 4) + c];
        ax += v.x * nr; ay += v.y * nr; az += v.z * nr; aw += v.w * nr;
    }
    ((float4*)out)[(size_t)node * (NC / 4) + c] = make_float4(ax, ay, az, aw);
}

// ---------------- +b2 and log_softmax, in place, warp per row --------------
__global__ void k_logsoftmax(float* __restrict__ out, const float* __restrict__ b2) {
    int t = blockIdx.x * blockDim.x + threadIdx.x;
    int r = t >> 5, lane = t & 31;
    if (r >= NN) return;
    float* row = out + (size_t)r * NC;
    float v0 = row[lane] + b2[lane];
    float v1 = (lane < NC - 32) ? row[32 + lane] + b2[32 + lane] : -INFINITY;
    float m = fmaxf(v0, v1);
#pragma unroll
    for (int o = 16; o; o >>= 1) m = fmaxf(m, __shfl_xor_sync(0xffffffffu, m, o));
    float s = expf(v0 - m) + ((lane < NC - 32) ? expf(v1 - m) : 0.f);
#pragma unroll
    for (int o = 16; o; o >>= 1) s += __shfl_xor_sync(0xffffffffu, s, o);
    float lse = m + logf(s);
    row[lane] = v0 - lse;
    if (lane < NC - 32) row[32 + lane] = v1 - lse;
}

// ---------------- launch ----------------
extern "C" void kernel_launch(void* const* d_in, const int* in_sizes, int n_in,
                              void* d_out, int out_size) {
    const float* x  = (const float*)d_in[0];
    const int*   ei = (const int*)  d_in[1];
    const int*   src = ei;
    const int*   dst = ei + NE;
    const float* W1 = (const float*)d_in[2];
    const float* b1 = (const float*)d_in[3];
    const float* W2 = (const float*)d_in[4];
    const float* b2 = (const float*)d_in[5];
    float* out = (float*)d_out;

    // Resolve REAL device addresses of scratch (host shadow trap — round 11).
    void *p_aggx = nullptr, *p_h = nullptr, *p_g = nullptr;
    cudaGetSymbolAddress(&p_aggx, g_aggx4);
    cudaGetSymbolAddress(&p_h,    g_h4);
    cudaGetSymbolAddress(&p_g,    g_g4);
    float* aggx = (float*)p_aggx;
    float* h    = (float*)p_h;
    float* g    = (float*)p_g;

    const int SMEM = (128 * STR * 2 + 64 * STR * 2) * sizeof(float);
    cudaFuncSetAttribute(k_mma_gemm<true,  true >,
                         cudaFuncAttributeMaxDynamicSharedMemorySize, SMEM);
    cudaFuncSetAttribute(k_mma_gemm<false, false>,
                         cudaFuncAttributeMaxDynamicSharedMemorySize, SMEM);

    // ---- CSR build: hist -> scan -> fill ----
    k_zero<<<NB, 256>>>();
    k_hist<<<(NE + 255) / 256, 256>>>(dst);
    k_dinv<<<NB, 256>>>();
    k_bsum<<<NB, 256>>>();
    k_bscan<<<1, 512>>>();
    k_offsets<<<NB, 256>>>();
    k_fill<<<(NE + 255) / 256, 256>>>(src, dst);

    // ---- layer 1: aggx = A~ x (gather, no fp atomics) ----
    k_gather_x<<<(NN * 32 + 255) / 256, 256>>>(x);

    const int gridM = (NN + 127) / 128;  // 782

    // h = relu(aggx @ W1 + b1)
    {
        dim3 grid(NH / 64, gridM);
        k_mma_gemm<true, true><<<grid, 256, SMEM>>>(aggx, W1, b1, h, NN, NH, NF);
    }
    // g = h @ W2
    {
        dim3 grid(1, gridM);
        k_mma_gemm<false, false><<<grid, 256, SMEM>>>(h, W2, nullptr, g, NN, NC, NH);
    }

    // ---- layer 2: out = A~ g (gather into d_out) ----
    k_gather_g<<<(NN * 16 + 255) / 256, 256>>>(out);

    // out = log_softmax(out + b2)
    k_logsoftmax<<<(NN * 32 + 255) / 256, 256>>>(out, b2);
}

// round 16
// speedup vs baseline: 1.3772x; 1.0805x over previous
#include <cuda_runtime.h>
#include <math.h>
#include <stdint.h>

#define NN 100000   // nodes
#define NF 128      // in feats
#define NH 256      // hidden
#define NC 40      // classes
#define NE 800000   // edges
#define NB ((NN + 255) / 256)   // 391 scan blocks

// ---------------- scratch (static device memory; no allocs) ----------------
__device__ float  g_dinv [NN];
__device__ int    g_cnt  [NN];
__device__ int    g_off  [NN];
__device__ int    g_cur  [NN];
__device__ int    g_adj  [NE];
__device__ int    g_bsum [NB + 1];
__device__ int    g_boff [NB + 1];
__device__ float4 g_aggx4[NN * NF / 4];
__device__ float4 g_h4   [NN * NH / 4];
__device__ float4 g_g4   [NN * NC / 4];

// ---------------- base-target PTX helpers ----------------
__device__ __forceinline__ void split_tf32(float a, uint32_t& hi, uint32_t& lo) {
    asm("cvt.rna.tf32.f32 %0, %1;" : "=r"(hi) : "f"(a));
    float r = a - __uint_as_float(hi);
    asm("cvt.rna.tf32.f32 %0, %1;" : "=r"(lo) : "f"(r));
}
__device__ __forceinline__ void mma16n8k8(float* d, const uint32_t* a, const uint32_t* b) {
    asm volatile(
        "mma.sync.aligned.m16n8k8.row.col.f32.tf32.tf32.f32 "
        "{%0,%1,%2,%3}, {%4,%5,%6,%7}, {%8,%9}, {%0,%1,%2,%3};"
        : "+f"(d[0]), "+f"(d[1]), "+f"(d[2]), "+f"(d[3])
        : "r"(a[0]), "r"(a[1]), "r"(a[2]), "r"(a[3]), "r"(b[0]), "r"(b[1]));
}

// ---------------- CSR build ----------------
__global__ void k_zero() {
    int i = blockIdx.x * blockDim.x + threadIdx.x;
    if (i < NN) g_cnt[i] = 0;
}
__global__ void k_hist(const int* __restrict__ dst) {
    int e = blockIdx.x * blockDim.x + threadIdx.x;
    if (e < NE) atomicAdd(&g_cnt[dst[e]], 1);
}
__global__ void k_dinv() {
    int i = blockIdx.x * blockDim.x + threadIdx.x;
    if (i < NN) g_dinv[i] = rsqrtf((float)(g_cnt[i] + 1));
}
__global__ void k_bsum() {
    __shared__ int sh[256];
    int t = threadIdx.x, i = blockIdx.x * 256 + t;
    int v = (i < NN) ? g_cnt[i] : 0;
    sh[t] = v; __syncthreads();
    for (int off = 128; off; off >>= 1) {
        if (t < off) sh[t] += sh[t + off];
        __syncthreads();
    }
    if (t == 0) g_bsum[blockIdx.x] = sh[0];
}
__global__ void k_bscan() {
    __shared__ int sh[512];
    int t = threadIdx.x;
    int v = (t < NB) ? g_bsum[t] : 0;
    sh[t] = v; __syncthreads();
    for (int off = 1; off < 512; off <<= 1) {
        int tv = (t >= off) ? sh[t - off] : 0;
        __syncthreads();
        sh[t] += tv;
        __syncthreads();
    }
    if (t < NB) g_boff[t] = sh[t] - v;
}
__global__ void k_offsets() {
    __shared__ int sh[256];
    int t = threadIdx.x, i = blockIdx.x * 256 + t;
    int v = (i < NN) ? g_cnt[i] : 0;
    sh[t] = v; __syncthreads();
    for (int off = 1; off < 256; off <<= 1) {
        int tv = (t >= off) ? sh[t - off] : 0;
        __syncthreads();
        sh[t] += tv;
        __syncthreads();
    }
    if (i < NN) {
        int o = g_boff[blockIdx.x] + sh[t] - v;
        g_off[i] = o;
        g_cur[i] = o;
    }
}
__global__ void k_fill(const int* __restrict__ src, const int* __restrict__ dst) {
    int e = blockIdx.x * blockDim.x + threadIdx.x;
    if (e >= NE) return;
    int d = dst[e];
    int p = atomicAdd(&g_cur[d], 1);
    g_adj[p] = src[e];
}

// ---------------- layer-1 gather: aggx = A~ x (warp per node) --------------
__global__ void k_gather_x(const float* __restrict__ x) {
    int t = blockIdx.x * blockDim.x + threadIdx.x;
    int w = t >> 5, lane = t & 31;
    if (w >= NN) return;
    const float4* x4 = (const float4*)x;
    float di = g_dinv[w];
    float4 a = x4[(size_t)w * 32 + lane];
    float s2 = di * di;
    float ax = a.x * s2, ay = a.y * s2, az = a.z * s2, aw = a.w * s2;
    int beg = g_off[w], n = g_cnt[w];
    int j = 0;
    for (; j + 4 <= n; j += 4) {
        int s0 = g_adj[beg + j], s1 = g_adj[beg + j + 1];
        int s2i = g_adj[beg + j + 2], s3 = g_adj[beg + j + 3];
        float n0 = di * g_dinv[s0], n1 = di * g_dinv[s1];
        float n2 = di * g_dinv[s2i], n3 = di * g_dinv[s3];
        float4 v0 = x4[(size_t)s0 * 32 + lane];
        float4 v1 = x4[(size_t)s1 * 32 + lane];
        float4 v2 = x4[(size_t)s2i * 32 + lane];
        float4 v3 = x4[(size_t)s3 * 32 + lane];
        ax += v0.x * n0 + v1.x * n1 + v2.x * n2 + v3.x * n3;
        ay += v0.y * n0 + v1.y * n1 + v2.y * n2 + v3.y * n3;
        az += v0.z * n0 + v1.z * n1 + v2.z * n2 + v3.z * n3;
        aw += v0.w * n0 + v1.w * n1 + v2.w * n2 + v3.w * n3;
    }
    for (; j < n; j++) {
        int s = g_adj[beg + j];
        float nr = di * g_dinv[s];
        float4 v = x4[(size_t)s * 32 + lane];
        ax += v.x * nr; ay += v.y * nr; az += v.z * nr; aw += v.w * nr;
    }
    g_aggx4[(size_t)w * 32 + lane] = make_float4(ax, ay, az, aw);
}

// ---------------- GEMM1: 128x64 tile, double-buffered, tf32x3 --------------
#define STR 36
#define ABUF (128 * STR)
#define BBUF (64 * STR)
template<bool BIAS, bool RELU>
__global__ void __launch_bounds__(256)
k_mma_gemm(const float* __restrict__ A, const float* __restrict__ Bw,
           const float* __restrict__ bias, float* __restrict__ C,
           int M, int N, int K) {
    extern __shared__ float sm[];
    float* As_hi = sm;                       // [2][128*STR]
    float* As_lo = As_hi + 2 * ABUF;
    float* Bs_hi = As_lo + 2 * ABUF;         // [2][64*STR]
    float* Bs_lo = Bs_hi + 2 * BBUF;

    const int tid = threadIdx.x;
    const int wid = tid >> 5, lid = tid & 31;
    const int wm = wid & 3, wn = wid >> 2;
    const int g = lid >> 2, tig = lid & 3;
    const int mBase = blockIdx.y * 128;
    const int colBase = blockIdx.x * 64;

    float d[2][4][4];
#pragma unroll
    for (int a = 0; a < 2; a++)
#pragma unroll
        for (int b = 0; b < 4; b++)
#pragma unroll
            for (int c = 0; c < 4; c++) d[a][b][c] = 0.f;

    const int KB = K >> 5;
    float4 ra[4];
    float rb[8];
    // prefetch chunk 0
#pragma unroll
    for (int u = 0; u < 4; u++) {
        int i = tid + u * 256;
        int m = i >> 3, q = (i & 7) << 2;
        int gm = mBase + m;
        ra[u] = (gm < M) ? *(const float4*)&A[(size_t)gm * K + q]
                         : make_float4(0.f, 0.f, 0.f, 0.f);
    }
#pragma unroll
    for (int u = 0; u < 8; u++) {
        int i = tid + u * 256;
        int kc = i >> 6, n = i & 63;
        int gn = colBase + n;
        rb[u] = (gn < N) ? Bw[(size_t)kc * N + gn] : 0.f;
    }

    for (int kb = 0; kb < KB; kb++) {
        const int bo = kb & 1;
        float* Ah = As_hi + bo * ABUF;
        float* Al = As_lo + bo * ABUF;
        float* Bh = Bs_hi + bo * BBUF;
        float* Bl = Bs_lo + bo * BBUF;
        // store regs -> smem (split)
#pragma unroll
        for (int u = 0; u < 4; u++) {
            int i = tid + u * 256;
            int m = i >> 3, q = (i & 7) << 2;
            uint32_t h0, l0, h1, l1, h2, l2, h3, l3;
            split_tf32(ra[u].x, h0, l0); split_tf32(ra[u].y, h1, l1);
            split_tf32(ra[u].z, h2, l2); split_tf32(ra[u].w, h3, l3);
            float* ph = Ah + m * STR + q;
            float* pl = Al + m * STR + q;
            ph[0] = __uint_as_float(h0); ph[1] = __uint_as_float(h1);
            ph[2] = __uint_as_float(h2); ph[3] = __uint_as_float(h3);
            pl[0] = __uint_as_float(l0); pl[1] = __uint_as_float(l1);
            pl[2] = __uint_as_float(l2); pl[3] = __uint_as_float(l3);
        }
#pragma unroll
        for (int u = 0; u < 8; u++) {
            int i = tid + u * 256;
            int kc = i >> 6, n = i & 63;
            uint32_t hi, lo; split_tf32(rb[u], hi, lo);
            Bh[n * STR + kc] = __uint_as_float(hi);
            Bl[n * STR + kc] = __uint_as_float(lo);
        }
        __syncthreads();
        // prefetch next chunk (overlaps MMA below)
        if (kb + 1 < KB) {
            const int kpos = (kb + 1) << 5;
#pragma unroll
            for (int u = 0; u < 4; u++) {
                int i = tid + u * 256;
                int m = i >> 3, q = (i & 7) << 2;
                int gm = mBase + m;
                ra[u] = (gm < M) ? *(const float4*)&A[(size_t)gm * K + kpos + q]
                                 : make_float4(0.f, 0.f, 0.f, 0.f);
            }
#pragma unroll
            for (int u = 0; u < 8; u++) {
                int i = tid + u * 256;
                int kc = i >> 6, n = i & 63;
                int gn = colBase + n;
                rb[u] = (gn < N) ? Bw[(size_t)(kpos + kc) * N + gn] : 0.f;
            }
        }
        // compute on buffer bo
#pragma unroll
        for (int ks = 0; ks < 4; ks++) {
            const int k0 = (ks << 3) + tig;
            uint32_t ah[2][4], al[2][4], bh[4][2], bl[4][2];
#pragma unroll
            for (int im = 0; im < 2; im++) {
                int r0 = (wm * 32 + im * 16 + g) * STR;
                ah[im][0] = __float_as_uint(Ah[r0 + k0]);
                ah[im][1] = __float_as_uint(Ah[r0 + 8 * STR + k0]);
                ah[im][2] = __float_as_uint(Ah[r0 + k0 + 4]);
                ah[im][3] = __float_as_uint(Ah[r0 + 8 * STR + k0 + 4]);
                al[im][0] = __float_as_uint(Al[r0 + k0]);
                al[im][1] = __float_as_uint(Al[r0 + 8 * STR + k0]);
                al[im][2] = __float_as_uint(Al[r0 + k0 + 4]);
                al[im][3] = __float_as_uint(Al[r0 + 8 * STR + k0 + 4]);
            }
#pragma unroll
            for (int in_ = 0; in_ < 4; in_++) {
                int n0 = (wn * 32 + in_ * 8 + g) * STR;
                bh[in_][0] = __float_as_uint(Bh[n0 + k0]);
                bh[in_][1] = __float_as_uint(Bh[n0 + k0 + 4]);
                bl[in_][0] = __float_as_uint(Bl[n0 + k0]);
                bl[in_][1] = __float_as_uint(Bl[n0 + k0 + 4]);
            }
#pragma unroll
            for (int im = 0; im < 2; im++)
#pragma unroll
                for (int in_ = 0; in_ < 4; in_++)
                    mma16n8k8(d[im][in_], ah[im], bh[in_]);
#pragma unroll
            for (int im = 0; im < 2; im++)
#pragma unroll
                for (int in_ = 0; in_ < 4; in_++)
                    mma16n8k8(d[im][in_], ah[im], bl[in_]);
#pragma unroll
            for (int im = 0; im < 2; im++)
#pragma unroll
                for (int in_ = 0; in_ < 4; in_++)
                    mma16n8k8(d[im][in_], al[im], bh[in_]);
        }
        __syncthreads();
    }

#pragma unroll
    for (int im = 0; im < 2; im++) {
        int r0 = mBase + wm * 32 + im * 16 + g;
        int r1 = r0 + 8;
#pragma unroll
        for (int in_ = 0; in_ < 4; in_++) {
            int c = colBase + wn * 32 + in_ * 8 + 2 * tig;
            if (c >= N) continue;
            float bx = 0.f, by = 0.f;
            if (BIAS) { bx = bias[c]; by = bias[c + 1]; }
            float v0 = d[im][in_][0] + bx, v1 = d[im][in_][1] + by;
            float v2 = d[im][in_][2] + bx, v3 = d[im][in_][3] + by;
            if (RELU) {
                v0 = fmaxf(v0, 0.f); v1 = fmaxf(v1, 0.f);
                v2 = fmaxf(v2, 0.f); v3 = fmaxf(v3, 0.f);
            }
            if (r0 < M) *(float2*)&C[(size_t)r0 * N + c] = make_float2(v0, v1);
            if (r1 < M) *(float2*)&C[(size_t)r1 * N + c] = make_float2(v2, v3);
        }
    }
}

// ---------------- GEMM2: 128x40 tile (no N padding), double-buffered -------
// 8 warps stacked in M (16 rows each), warp tile 16x40 (5 n-frags).
#define B40 (40 * STR)
__global__ void __launch_bounds__(256)
k_mma_gemm40(const float* __restrict__ A, const float* __restrict__ Bw,
             float* __restrict__ C, int M) {
    const int K = NH, N = NC;
    extern __shared__ float sm[];
    float* As_hi = sm;                       // [2][128*STR]
    float* As_lo = As_hi + 2 * ABUF;
    float* Bs_hi = As_lo + 2 * ABUF;         // [2][40*STR]
    float* Bs_lo = Bs_hi + 2 * B40;

    const int tid = threadIdx.x;
    const int wid = tid >> 5, lid = tid & 31;
    const int g = lid >> 2, tig = lid & 3;
    const int mBase = blockIdx.x * 128;

    float d[5][4];
#pragma unroll
    for (int b = 0; b < 5; b++)
#pragma unroll
        for (int c = 0; c < 4; c++) d[b][c] = 0.f;

    const int KB = K >> 5;   // 8
    float4 ra[4];
    float rb[5];
#pragma unroll
    for (int u = 0; u < 4; u++) {
        int i = tid + u * 256;
        int m = i >> 3, q = (i & 7) << 2;
        int gm = mBase + m;
        ra[u] = (gm < M) ? *(const float4*)&A[(size_t)gm * K + q]
                         : make_float4(0.f, 0.f, 0.f, 0.f);
    }
#pragma unroll
    for (int u = 0; u < 5; u++) {
        int i = tid + u * 256;
        int kc = i / 40, n = i - kc * 40;
        rb[u] = Bw[(size_t)kc * N + n];
    }

    for (int kb = 0; kb < KB; kb++) {
        const int bo = kb & 1;
        float* Ah = As_hi + bo * ABUF;
        float* Al = As_lo + bo * ABUF;
        float* Bh = Bs_hi + bo * B40;
        float* Bl = Bs_lo + bo * B40;
#pragma unroll
        for (int u = 0; u < 4; u++) {
            int i = tid + u * 256;
            int m = i >> 3, q = (i & 7) << 2;
            uint32_t h0, l0, h1, l1, h2, l2, h3, l3;
            split_tf32(ra[u].x, h0, l0); split_tf32(ra[u].y, h1, l1);
            split_tf32(ra[u].z, h2, l2); split_tf32(ra[u].w, h3, l3);
            float* ph = Ah + m * STR + q;
            float* pl = Al + m * STR + q;
            ph[0] = __uint_as_float(h0); ph[1] = __uint_as_float(h1);
            ph[2] = __uint_as_float(h2); ph[3] = __uint_as_float(h3);
            pl[0] = __uint_as_float(l0); pl[1] = __uint_as_float(l1);
            pl[2] = __uint_as_float(l2); pl[3] = __uint_as_float(l3);
        }
#pragma unroll
        for (int u = 0; u < 5; u++) {
            int i = tid + u * 256;
            int kc = i / 40, n = i - kc * 40;
            uint32_t hi, lo; split_tf32(rb[u], hi, lo);
            Bh[n * STR + kc] = __uint_as_float(hi);
            Bl[n * STR + kc] = __uint_as_float(lo);
        }
        __syncthreads();
        if (kb + 1 < KB) {
            const int kpos = (kb + 1) << 5;
#pragma unroll
            for (int u = 0; u < 4; u++) {
                int i = tid + u * 256;
                int m = i >> 3, q = (i & 7) << 2;
                int gm = mBase + m;
                ra[u] = (gm < M) ? *(const float4*)&A[(size_t)gm * K + kpos + q]
                                 : make_float4(0.f, 0.f, 0.f, 0.f);
            }
#pragma unroll
            for (int u = 0; u < 5; u++) {
                int i = tid + u * 256;
                int kc = i / 40, n = i - kc * 40;
                rb[u] = Bw[(size_t)(kpos + kc) * N + n];
            }
        }
#pragma unroll
        for (int ks = 0; ks < 4; ks++) {
            const int k0 = (ks << 3) + tig;
            uint32_t ah[4], al[4], bh[5][2], bl[5][2];
            {
                int r0 = (wid * 16 + g) * STR;
                ah[0] = __float_as_uint(Ah[r0 + k0]);
                ah[1] = __float_as_uint(Ah[r0 + 8 * STR + k0]);
                ah[2] = __float_as_uint(Ah[r0 + k0 + 4]);
                ah[3] = __float_as_uint(Ah[r0 + 8 * STR + k0 + 4]);
                al[0] = __float_as_uint(Al[r0 + k0]);
                al[1] = __float_as_uint(Al[r0 + 8 * STR + k0]);
                al[2] = __float_as_uint(Al[r0 + k0 + 4]);
                al[3] = __float_as_uint(Al[r0 + 8 * STR + k0 + 4]);
            }
#pragma unroll
            for (int in_ = 0; in_ < 5; in_++) {
                int n0 = (in_ * 8 + g) * STR;
                bh[in_][0] = __float_as_uint(Bh[n0 + k0]);
                bh[in_][1] = __float_as_uint(Bh[n0 + k0 + 4]);
                bl[in_][0] = __float_as_uint(Bl[n0 + k0]);
                bl[in_][1] = __float_as_uint(Bl[n0 + k0 + 4]);
            }
#pragma unroll
            for (int in_ = 0; in_ < 5; in_++) mma16n8k8(d[in_], ah, bh[in_]);
#pragma unroll
            for (int in_ = 0; in_ < 5; in_++) mma16n8k8(d[in_], ah, bl[in_]);
#pragma unroll
            for (int in_ = 0; in_ < 5; in_++) mma16n8k8(d[in_], al, bh[in_]);
        }
        __syncthreads();
    }

    int r0 = mBase + wid * 16 + g;
    int r1 = r0 + 8;
#pragma unroll
    for (int in_ = 0; in_ < 5; in_++) {
        int c = in_ * 8 + 2 * tig;
        if (r0 < M) *(float2*)&C[(size_t)r0 * N + c] = make_float2(d[in_][0], d[in_][1]);
        if (r1 < M) *(float2*)&C[(size_t)r1 * N + c] = make_float2(d[in_][2], d[in_][3]);
    }
}

// ---------------- layer-2 gather: out = A~ g (2 nodes per warp) ------------
__global__ void k_gather_g(float* __restrict__ out) {
    int t = blockIdx.x * blockDim.x + threadIdx.x;
    int w = t >> 5, lane = t & 31;
    int node = w * 2 + (lane >> 4);
    int c = lane & 15;
    if (node >= NN || c >= NC / 4) return;
    float di = g_dinv[node];
    float s2 = di * di;
    float4 a = g_g4[(size_t)node * (NC / 4) + c];
    float ax = a.x * s2, ay = a.y * s2, az = a.z * s2, aw = a.w * s2;
    int beg = g_off[node], n = g_cnt[node];
    int j = 0;
    for (; j + 2 <= n; j += 2) {
        int s0 = g_adj[beg + j], s1 = g_adj[beg + j + 1];
        float n0 = di * g_dinv[s0], n1 = di * g_dinv[s1];
        float4 v0 = g_g4[(size_t)s0 * (NC / 4) + c];
        float4 v1 = g_g4[(size_t)s1 * (NC / 4) + c];
        ax += v0.x * n0 + v1.x * n1; ay += v0.y * n0 + v1.y * n1;
        az += v0.z * n0 + v1.z * n1; aw += v0.w * n0 + v1.w * n1;
    }
    for (; j < n; j++) {
        int s = g_adj[beg + j];
        float nr = di * g_dinv[s];
        float4 v = g_g4[(size_t)s * (NC / 4) + c];
        ax += v.x * nr; ay += v.y * nr; az += v.z * nr; aw += v.w * nr;
    }
    ((float4*)out)[(size_t)node * (NC / 4) + c] = make_float4(ax, ay, az, aw);
}

// ---------------- +b2 and log_softmax, in place, warp per row --------------
__global__ void k_logsoftmax(float* __restrict__ out, const float* __restrict__ b2) {
    int t = blockIdx.x * blockDim.x + threadIdx.x;
    int r = t >> 5, lane = t & 31;
    if (r >= NN) return;
    float* row = out + (size_t)r * NC;
    float v0 = row[lane] + b2[lane];
    float v1 = (lane < NC - 32) ? row[32 + lane] + b2[32 + lane] : -INFINITY;
    float m = fmaxf(v0, v1);
#pragma unroll
    for (int o = 16; o; o >>= 1) m = fmaxf(m, __shfl_xor_sync(0xffffffffu, m, o));
    float s = expf(v0 - m) + ((lane < NC - 32) ? expf(v1 - m) : 0.f);
#pragma unroll
    for (int o = 16; o; o >>= 1) s += __shfl_xor_sync(0xffffffffu, s, o);
    float lse = m + logf(s);
    row[lane] = v0 - lse;
    if (lane < NC - 32) row[32 + lane] = v1 - lse;
}

// ---------------- launch ----------------
extern "C" void kernel_launch(void* const* d_in, const int* in_sizes, int n_in,
                              void* d_out, int out_size) {
    const float* x  = (const float*)d_in[0];
    const int*   ei = (const int*)  d_in[1];
    const int*   src = ei;
    const int*   dst = ei + NE;
    const float* W1 = (const float*)d_in[2];
    const float* b1 = (const float*)d_in[3];
    const float* W2 = (const float*)d_in[4];
    const float* b2 = (const float*)d_in[5];
    float* out = (float*)d_out;

    void *p_aggx = nullptr, *p_h = nullptr, *p_g = nullptr;
    cudaGetSymbolAddress(&p_aggx, g_aggx4);
    cudaGetSymbolAddress(&p_h,    g_h4);
    cudaGetSymbolAddress(&p_g,    g_g4);
    float* aggx = (float*)p_aggx;
    float* h    = (float*)p_h;
    float* g    = (float*)p_g;

    const int SMEM1 = (2 * ABUF * 2 + 2 * BBUF * 2) * (int)sizeof(float);  // 110592
    const int SMEM2 = (2 * ABUF * 2 + 2 * B40 * 2) * (int)sizeof(float);   //  96768
    cudaFuncSetAttribute(k_mma_gemm<true, true>,
                         cudaFuncAttributeMaxDynamicSharedMemorySize, SMEM1);
    cudaFuncSetAttribute(k_mma_gemm40,
                         cudaFuncAttributeMaxDynamicSharedMemorySize, SMEM2);

    // ---- CSR build ----
    k_zero<<<NB, 256>>>();
    k_hist<<<(NE + 255) / 256, 256>>>(dst);
    k_dinv<<<NB, 256>>>();
    k_bsum<<<NB, 256>>>();
    k_bscan<<<1, 512>>>();
    k_offsets<<<NB, 256>>>();
    k_fill<<<(NE + 255) / 256, 256>>>(src, dst);

    // ---- layer 1 ----
    k_gather_x<<<(NN * 32 + 255) / 256, 256>>>(x);

    const int gridM = (NN + 127) / 128;  // 782
    {
        dim3 grid(NH / 64, gridM);
        k_mma_gemm<true, true><<<grid, 256, SMEM1>>>(aggx, W1, b1, h, NN, NH, NF);
    }
    k_mma_gemm40<<<gridM, 256, SMEM2>>>(h, W2, g, NN);

    // ---- layer 2 ----
    k_gather_g<<<(NN * 16 + 255) / 256, 256>>>(out);
    k_logsoftmax<<<(NN * 32 + 255) / 256, 256>>>(out, b2);
}